// round 12
// baseline (speedup 1.0000x reference)
#include <cuda_runtime.h>
#include <cuda_fp16.h>

// ---------------------------------------------------------------------------
// GINBlock. R12: vectorized edge kernels (2 edges/thread), aggregate MLP=16,
// prep fusion (zero+convert+wprep). Keep: fp16 mirror gather -> tf32 h0,
// counting-sort CSR, fused tf32 MLP (GEMM1->smem->GEMM2), BN via red.v2.
// ---------------------------------------------------------------------------

#define GIN_N_MAX 100000
#define GIN_H 128
#define GIN_E_MAX 3200000
#define SCAN_B 1024
#define SCAN_NB ((GIN_N_MAX + SCAN_B - 1) / SCAN_B)   // 98

__device__ __half   g_xh[GIN_N_MAX * GIN_H];       // fp16 mirror of x
__device__ __align__(16) unsigned g_h0t[GIN_N_MAX * GIN_H];  // h0 in tf32 bits
__device__ int      g_deg[GIN_N_MAX];
__device__ int      g_off[GIN_N_MAX + 1];
__device__ int      g_cursor[GIN_N_MAX];
__device__ int      g_srcs[GIN_E_MAX];
__device__ int      g_bsum[SCAN_NB];
__device__ int      g_boff[SCAN_NB];
__device__ __align__(16) unsigned g_w1f[16384];    // W1 tf32 fragment order
__device__ __align__(16) unsigned g_w2f[16384];    // W2 tf32 fragment order
__device__ __align__(16) float g_sum[GIN_H];
__device__ __align__(16) float g_sq[GIN_H];
__device__ int      g_is64;

__device__ __forceinline__ unsigned f2tf(float f) {
    unsigned r;
    asm("cvt.rna.tf32.f32 %0, %1;" : "=r"(r) : "f"(f));
    return r;
}
__device__ __forceinline__ void mma_tf32(float* d, const unsigned* a, unsigned b0, unsigned b1) {
    asm("mma.sync.aligned.m16n8k8.row.col.f32.tf32.tf32.f32 "
        "{%0,%1,%2,%3}, {%4,%5,%6,%7}, {%8,%9}, {%0,%1,%2,%3};"
        : "+f"(d[0]), "+f"(d[1]), "+f"(d[2]), "+f"(d[3])
        : "r"(a[0]), "r"(a[1]), "r"(a[2]), "r"(a[3]), "r"(b0), "r"(b1));
}

// ---------------------------------------------------------------------------
// prep: zero deg/sums + int64 sniff + x->fp16 convert + W frag prep, fused.
// grid covers total4 (= N*32) threads.
// ---------------------------------------------------------------------------
__global__ void prep_kernel(const unsigned* __restrict__ ei,
                            const float4* __restrict__ x4,
                            const float* __restrict__ W1,
                            const float* __restrict__ W2,
                            int N, int total4) {
    int idx = blockIdx.x * blockDim.x + threadIdx.x;
    if (idx < N) g_deg[idx] = 0;
    if (idx < GIN_H) { g_sum[idx] = 0.f; g_sq[idx] = 0.f; }
    if (idx == 0) {
        int allz = 1;
#pragma unroll
        for (int i = 0; i < 16; i++) allz &= (ei[2 * i + 1] == 0u);
        g_is64 = allz;
    }
    if (idx < 8192) {   // W fragment prep
        int l = idx & 31, ntg = (idx >> 5) & 15, ks = idx >> 9;
        int k = ks * 8 + (l & 3);
        int n = ntg * 8 + (l >> 2);
        *(uint2*)&g_w1f[idx * 2] = make_uint2(f2tf(__ldg(&W1[k * 128 + n])),
                                              f2tf(__ldg(&W1[(k + 4) * 128 + n])));
        *(uint2*)&g_w2f[idx * 2] = make_uint2(f2tf(__ldg(&W2[k * 128 + n])),
                                              f2tf(__ldg(&W2[(k + 4) * 128 + n])));
    }
    if (idx < total4) {  // fp16 mirror
        float4 v = x4[idx];
        __half2 a = __floats2half2_rn(v.x, v.y);
        __half2 b = __floats2half2_rn(v.z, v.w);
        uint2 p;
        p.x = *(unsigned*)&a;
        p.y = *(unsigned*)&b;
        ((uint2*)g_xh)[idx] = p;
    }
}

// hist: 2 edges/thread, vectorized loads.
__global__ void hist_kernel(const void* __restrict__ ei, int E) {
    int t = blockIdx.x * blockDim.x + threadIdx.x;
    int e = t * 2;
    if (e >= E) return;
    int d0, d1;
    if (g_is64) {
        ulonglong2 dd = __ldg(&((const ulonglong2*)ei)[(E + e) >> 1]);
        d0 = (int)dd.x; d1 = (int)dd.y;
    } else {
        int2 dd = __ldg(&((const int2*)ei)[(E + e) >> 1]);
        d0 = dd.x; d1 = dd.y;
    }
    atomicAdd(&g_deg[d0], 1);
    if (e + 1 < E) atomicAdd(&g_deg[d1], 1);
}

// ---- 3-phase exclusive scan ----
__global__ void __launch_bounds__(SCAN_B)
scan1_kernel(int N) {
    __shared__ int sh[SCAN_B];
    int t = threadIdx.x;
    int i = blockIdx.x * SCAN_B + t;
    int v = (i < N) ? g_deg[i] : 0;
    sh[t] = v;
    __syncthreads();
#pragma unroll
    for (int d = 1; d < SCAN_B; d <<= 1) {
        int u = (t >= d) ? sh[t - d] : 0;
        __syncthreads();
        sh[t] += u;
        __syncthreads();
    }
    if (i < N) g_off[i] = sh[t] - v;
    if (t == SCAN_B - 1) g_bsum[blockIdx.x] = sh[t];
}

__global__ void __launch_bounds__(128)
scan2_kernel(int NB) {
    __shared__ int sh[128];
    int t = threadIdx.x;
    int v = (t < NB) ? g_bsum[t] : 0;
    sh[t] = v;
    __syncthreads();
#pragma unroll
    for (int d = 1; d < 128; d <<= 1) {
        int u = (t >= d) ? sh[t - d] : 0;
        __syncthreads();
        sh[t] += u;
        __syncthreads();
    }
    if (t < NB) g_boff[t] = sh[t] - v;
}

__global__ void scan3_kernel(int N, int E) {
    int i = blockIdx.x * blockDim.x + threadIdx.x;
    if (i >= N) return;
    int v = g_off[i] + g_boff[i >> 10];
    g_off[i] = v;
    g_cursor[i] = v;
    if (i == 0) g_off[N] = E;
}

// permute: 2 edges/thread, vectorized loads.
__global__ void permute_kernel(const void* __restrict__ ei, int E) {
    int t = blockIdx.x * blockDim.x + threadIdx.x;
    int e = t * 2;
    if (e >= E) return;
    int s0, s1, d0, d1;
    if (g_is64) {
        ulonglong2 ss = __ldg(&((const ulonglong2*)ei)[e >> 1]);
        ulonglong2 dd = __ldg(&((const ulonglong2*)ei)[(E + e) >> 1]);
        s0 = (int)ss.x; s1 = (int)ss.y;
        d0 = (int)dd.x; d1 = (int)dd.y;
    } else {
        int2 ss = __ldg(&((const int2*)ei)[e >> 1]);
        int2 dd = __ldg(&((const int2*)ei)[(E + e) >> 1]);
        s0 = ss.x; s1 = ss.y;
        d0 = dd.x; d1 = dd.y;
    }
    int p0 = atomicAdd(&g_cursor[d0], 1);
    g_srcs[p0] = s0;
    if (e + 1 < E) {
        int p1 = atomicAdd(&g_cursor[d1], 1);
        g_srcs[p1] = s1;
    }
}

// Warp/node CSR gather; 16-wide load batches (MLP=16); writes h0 as tf32.
__global__ void aggregate_kernel(const float4* __restrict__ x4, int N) {
    int idx = blockIdx.x * blockDim.x + threadIdx.x;
    int node = idx >> 5;
    int lane = idx & 31;
    if (node >= N) return;
    float4 acc = x4[node * 32 + lane];
    const uint2* xh = (const uint2*)g_xh;
    int e = g_off[node], end = g_off[node + 1];
    while (e < end) {
        int cnt = min(32, end - e);
        int myidx = (lane < cnt) ? __ldg(&g_srcs[e + lane]) : 0;
        int j = 0;
        for (; j + 16 <= cnt; j += 16) {
            uint2 p[16];
#pragma unroll
            for (int q = 0; q < 16; q++) {
                int s = __shfl_sync(0xffffffffu, myidx, j + q);
                p[q] = __ldg(&xh[s * 32 + lane]);
            }
#pragma unroll
            for (int q = 0; q < 16; q++) {
                float2 f01 = __half22float2(*(__half2*)&p[q].x);
                float2 f23 = __half22float2(*(__half2*)&p[q].y);
                acc.x += f01.x; acc.y += f01.y;
                acc.z += f23.x; acc.w += f23.y;
            }
        }
        if (j + 8 <= cnt) {
            uint2 p[8];
#pragma unroll
            for (int q = 0; q < 8; q++) {
                int s = __shfl_sync(0xffffffffu, myidx, j + q);
                p[q] = __ldg(&xh[s * 32 + lane]);
            }
#pragma unroll
            for (int q = 0; q < 8; q++) {
                float2 f01 = __half22float2(*(__half2*)&p[q].x);
                float2 f23 = __half22float2(*(__half2*)&p[q].y);
                acc.x += f01.x; acc.y += f01.y;
                acc.z += f23.x; acc.w += f23.y;
            }
            j += 8;
        }
        for (; j < cnt; j++) {
            int s = __shfl_sync(0xffffffffu, myidx, j);
            uint2 p = __ldg(&xh[s * 32 + lane]);
            float2 f01 = __half22float2(*(__half2*)&p.x);
            float2 f23 = __half22float2(*(__half2*)&p.y);
            acc.x += f01.x; acc.y += f01.y;
            acc.z += f23.x; acc.w += f23.y;
        }
        e += cnt;
    }
    ((uint4*)g_h0t)[node * 32 + lane] =
        make_uint4(f2tf(acc.x), f2tf(acc.y), f2tf(acc.z), f2tf(acc.w));
}

// ---------------------------------------------------------------------------
// Fused MLP: per 128-row tile: load tf32 h0 -> As -> GEMM1(+b1,relu) -> As
//            -> GEMM2(+b2,relu) -> out + BN stats.
// ---------------------------------------------------------------------------
#define AS_STRIDE 132
#define MLP_SMEM (128 * AS_STRIDE * 4)     // 67584 B

__global__ void __launch_bounds__(512, 2)
mlp_kernel(const float* __restrict__ bias1,
           const float* __restrict__ bias2,
           float* __restrict__ out, int N) {
    extern __shared__ unsigned As[];         // [128][AS_STRIDE]
    const int tid = threadIdx.x;
    const int lane = tid & 31;
    const int wid = tid >> 5;
    const int row0 = blockIdx.x * 128;

    const uint4* H04 = (const uint4*)g_h0t;
#pragma unroll
    for (int i = 0; i < 8; i++) {
        int s = i * 512 + tid;               // 0..4095
        int r = s >> 5, q = s & 31;
        uint4 v = make_uint4(0u, 0u, 0u, 0u);
        int gr = row0 + r;
        if (gr < N) v = H04[gr * 32 + q];
        *(uint4*)&As[r * AS_STRIDE + q * 4] = v;
    }
    __syncthreads();

    const int rg = wid >> 1, cg = wid & 1;
    float d[8][4];
#pragma unroll
    for (int nt = 0; nt < 8; nt++)
#pragma unroll
        for (int r = 0; r < 4; r++) d[nt][r] = 0.f;

    const int rbase = rg * 16 + (lane >> 2);
#pragma unroll
    for (int ksg = 0; ksg < 16; ksg++) {
        int k = ksg * 8 + (lane & 3);
        unsigned a[4];
        a[0] = As[rbase * AS_STRIDE + k];
        a[1] = As[(rbase + 8) * AS_STRIDE + k];
        a[2] = As[rbase * AS_STRIDE + k + 4];
        a[3] = As[(rbase + 8) * AS_STRIDE + k + 4];
#pragma unroll
        for (int nt = 0; nt < 8; nt++) {
            uint2 b = *(const uint2*)&g_w1f[((ksg * 16 + cg * 8 + nt) * 32 + lane) * 2];
            mma_tf32(d[nt], a, b.x, b.y);
        }
    }
    __syncthreads();

    // epilogue 1: bias+relu -> tf32 h1 back into As
#pragma unroll
    for (int nt = 0; nt < 8; nt++) {
        int col = cg * 64 + nt * 8 + 2 * (lane & 3);
        int r0 = rg * 16 + (lane >> 2);
        float b0 = __ldg(&bias1[col]);
        float b1v = __ldg(&bias1[col + 1]);
        float v0 = fmaxf(d[nt][0] + b0, 0.f);
        float v1 = fmaxf(d[nt][1] + b1v, 0.f);
        float v2 = fmaxf(d[nt][2] + b0, 0.f);
        float v3 = fmaxf(d[nt][3] + b1v, 0.f);
        *(uint2*)&As[r0 * AS_STRIDE + col] = make_uint2(f2tf(v0), f2tf(v1));
        *(uint2*)&As[(r0 + 8) * AS_STRIDE + col] = make_uint2(f2tf(v2), f2tf(v3));
#pragma unroll
        for (int r = 0; r < 4; r++) d[nt][r] = 0.f;
    }
    __syncthreads();

    // GEMM2
#pragma unroll
    for (int ksg = 0; ksg < 16; ksg++) {
        int k = ksg * 8 + (lane & 3);
        unsigned a[4];
        a[0] = As[rbase * AS_STRIDE + k];
        a[1] = As[(rbase + 8) * AS_STRIDE + k];
        a[2] = As[rbase * AS_STRIDE + k + 4];
        a[3] = As[(rbase + 8) * AS_STRIDE + k + 4];
#pragma unroll
        for (int nt = 0; nt < 8; nt++) {
            uint2 b = *(const uint2*)&g_w2f[((ksg * 16 + cg * 8 + nt) * 32 + lane) * 2];
            mma_tf32(d[nt], a, b.x, b.y);
        }
    }

    // epilogue 2: bias+relu -> out + BN stats
#pragma unroll
    for (int nt = 0; nt < 8; nt++) {
        int col = cg * 64 + nt * 8 + 2 * (lane & 3);
        int r0 = row0 + rg * 16 + (lane >> 2);
        float b0 = __ldg(&bias2[col]);
        float b1v = __ldg(&bias2[col + 1]);
        float v0 = fmaxf(d[nt][0] + b0, 0.f);
        float v1 = fmaxf(d[nt][1] + b1v, 0.f);
        float v2 = fmaxf(d[nt][2] + b0, 0.f);
        float v3 = fmaxf(d[nt][3] + b1v, 0.f);
        bool ok0 = (r0 < N), ok1 = (r0 + 8 < N);
        if (ok0) *(float2*)&out[r0 * 128 + col] = make_float2(v0, v1);
        if (ok1) *(float2*)&out[(r0 + 8) * 128 + col] = make_float2(v2, v3);
        float s0 = (ok0 ? v0 : 0.f) + (ok1 ? v2 : 0.f);
        float s1 = (ok0 ? v1 : 0.f) + (ok1 ? v3 : 0.f);
        float q0 = (ok0 ? v0 * v0 : 0.f) + (ok1 ? v2 * v2 : 0.f);
        float q1 = (ok0 ? v1 * v1 : 0.f) + (ok1 ? v3 * v3 : 0.f);
#pragma unroll
        for (int m = 16; m >= 4; m >>= 1) {
            s0 += __shfl_xor_sync(0xffffffffu, s0, m);
            s1 += __shfl_xor_sync(0xffffffffu, s1, m);
            q0 += __shfl_xor_sync(0xffffffffu, q0, m);
            q1 += __shfl_xor_sync(0xffffffffu, q1, m);
        }
        if (lane < 4) {
            asm volatile("red.global.add.v2.f32 [%0], {%1, %2};"
                         :: "l"(&g_sum[col]), "f"(s0), "f"(s1) : "memory");
            asm volatile("red.global.add.v2.f32 [%0], {%1, %2};"
                         :: "l"(&g_sq[col]), "f"(q0), "f"(q1) : "memory");
        }
    }
}

// BN apply; per-block recompute of scale/shift from global sums.
__global__ void apply_bn_kernel(float4* __restrict__ out,
                                const float* __restrict__ gamma,
                                const float* __restrict__ beta,
                                float invN, int total4) {
    __shared__ float s_scale[GIN_H], s_shift[GIN_H];
    int t = threadIdx.x;
    if (t < GIN_H) {
        float mean = g_sum[t] * invN;
        float var = fmaf(-mean, mean, g_sq[t] * invN);
        float sc = gamma[t] * rsqrtf(var + 1e-5f);
        s_scale[t] = sc;
        s_shift[t] = fmaf(-mean, sc, beta[t]);
    }
    __syncthreads();
    int idx = blockIdx.x * blockDim.x + t;
    if (idx >= total4) return;
    int c = (idx & 31) * 4;
    float4 v = out[idx];
    v.x = fmaf(v.x, s_scale[c + 0], s_shift[c + 0]);
    v.y = fmaf(v.y, s_scale[c + 1], s_shift[c + 1]);
    v.z = fmaf(v.z, s_scale[c + 2], s_shift[c + 2]);
    v.w = fmaf(v.w, s_scale[c + 3], s_shift[c + 3]);
    out[idx] = v;
}

// ---------------------------------------------------------------------------
// Inputs: x, edge_index, edge_attr, W1, b1, W2, b2, gamma, beta
// ---------------------------------------------------------------------------
extern "C" void kernel_launch(void* const* d_in, const int* in_sizes, int n_in,
                              void* d_out, int out_size) {
    const float* x     = (const float*)d_in[0];
    const void*  ei    = d_in[1];
    const float* W1    = (const float*)d_in[3];
    const float* b1    = (const float*)d_in[4];
    const float* W2    = (const float*)d_in[5];
    const float* b2    = (const float*)d_in[6];
    const float* gamma = (const float*)d_in[7];
    const float* beta  = (const float*)d_in[8];
    float* out = (float*)d_out;

    int N = in_sizes[0] / GIN_H;
    int E = in_sizes[1] / 2;

    cudaFuncSetAttribute(mlp_kernel,
                         cudaFuncAttributeMaxDynamicSharedMemorySize, MLP_SMEM);

    int total4 = N * (GIN_H / 4);
    int eb2 = (E / 2 + 255) / 256;
    int nb = (N + SCAN_B - 1) / SCAN_B;

    prep_kernel<<<(total4 + 255) / 256, 256>>>((const unsigned*)ei,
                                               (const float4*)x, W1, W2, N, total4);
    hist_kernel<<<eb2, 256>>>(ei, E);
    scan1_kernel<<<nb, SCAN_B>>>(N);
    scan2_kernel<<<1, 128>>>(nb);
    scan3_kernel<<<(N + 255) / 256, 256>>>(N, E);
    permute_kernel<<<eb2, 256>>>(ei, E);

    long long agg_items = (long long)N * 32;
    aggregate_kernel<<<(int)((agg_items + 255) / 256), 256>>>((const float4*)x, N);

    int tiles = (N + 127) / 128;
    mlp_kernel<<<tiles, 512, MLP_SMEM>>>(b1, b2, out, N);

    apply_bn_kernel<<<(total4 + 255) / 256, 256>>>((float4*)out, gamma, beta,
                                                   1.0f / (float)N, total4);
}

// round 13
// speedup vs baseline: 1.0432x; 1.0432x over previous
#include <cuda_runtime.h>
#include <cuda_fp16.h>

// ---------------------------------------------------------------------------
// GINBlock. R13: revert R12's regressions (back to R11 config: MLP=8
// aggregate, 1-edge/thread hist+permute). Keep prep fusion; fold scan2 into
// scan3 (each block redundantly scans the <=98 block sums in smem).
// Pipeline: prep -> hist -> scan1 -> scan23 -> permute -> aggregate(fp16
// gather -> tf32 h0) -> fused tf32 MLP (GEMM1->smem->GEMM2 + BN stats) ->
// BN apply.
// ---------------------------------------------------------------------------

#define GIN_N_MAX 100000
#define GIN_H 128
#define GIN_E_MAX 3200000
#define SCAN_B 1024
#define SCAN_NB ((GIN_N_MAX + SCAN_B - 1) / SCAN_B)   // 98

__device__ __half   g_xh[GIN_N_MAX * GIN_H];       // fp16 mirror of x
__device__ __align__(16) unsigned g_h0t[GIN_N_MAX * GIN_H];  // h0 in tf32 bits
__device__ int      g_deg[GIN_N_MAX];
__device__ int      g_off[GIN_N_MAX + 1];
__device__ int      g_cursor[GIN_N_MAX];
__device__ int      g_srcs[GIN_E_MAX];
__device__ int      g_bsum[SCAN_NB];
__device__ __align__(16) unsigned g_w1f[16384];    // W1 tf32 fragment order
__device__ __align__(16) unsigned g_w2f[16384];    // W2 tf32 fragment order
__device__ __align__(16) float g_sum[GIN_H];
__device__ __align__(16) float g_sq[GIN_H];
__device__ int      g_is64;

__device__ __forceinline__ unsigned f2tf(float f) {
    unsigned r;
    asm("cvt.rna.tf32.f32 %0, %1;" : "=r"(r) : "f"(f));
    return r;
}
__device__ __forceinline__ void mma_tf32(float* d, const unsigned* a, unsigned b0, unsigned b1) {
    asm("mma.sync.aligned.m16n8k8.row.col.f32.tf32.tf32.f32 "
        "{%0,%1,%2,%3}, {%4,%5,%6,%7}, {%8,%9}, {%0,%1,%2,%3};"
        : "+f"(d[0]), "+f"(d[1]), "+f"(d[2]), "+f"(d[3])
        : "r"(a[0]), "r"(a[1]), "r"(a[2]), "r"(a[3]), "r"(b0), "r"(b1));
}

// ---------------------------------------------------------------------------
// prep: zero deg/sums + int64 sniff + x->fp16 convert + W frag prep, fused.
// ---------------------------------------------------------------------------
__global__ void prep_kernel(const unsigned* __restrict__ ei,
                            const float4* __restrict__ x4,
                            const float* __restrict__ W1,
                            const float* __restrict__ W2,
                            int N, int total4) {
    int idx = blockIdx.x * blockDim.x + threadIdx.x;
    if (idx < N) g_deg[idx] = 0;
    if (idx < GIN_H) { g_sum[idx] = 0.f; g_sq[idx] = 0.f; }
    if (idx == 0) {
        int allz = 1;
#pragma unroll
        for (int i = 0; i < 16; i++) allz &= (ei[2 * i + 1] == 0u);
        g_is64 = allz;
    }
    if (idx < 8192) {   // W fragment prep
        int l = idx & 31, ntg = (idx >> 5) & 15, ks = idx >> 9;
        int k = ks * 8 + (l & 3);
        int n = ntg * 8 + (l >> 2);
        *(uint2*)&g_w1f[idx * 2] = make_uint2(f2tf(__ldg(&W1[k * 128 + n])),
                                              f2tf(__ldg(&W1[(k + 4) * 128 + n])));
        *(uint2*)&g_w2f[idx * 2] = make_uint2(f2tf(__ldg(&W2[k * 128 + n])),
                                              f2tf(__ldg(&W2[(k + 4) * 128 + n])));
    }
    if (idx < total4) {  // fp16 mirror
        float4 v = x4[idx];
        __half2 a = __floats2half2_rn(v.x, v.y);
        __half2 b = __floats2half2_rn(v.z, v.w);
        uint2 p;
        p.x = *(unsigned*)&a;
        p.y = *(unsigned*)&b;
        ((uint2*)g_xh)[idx] = p;
    }
}

// hist: 1 edge/thread (R11 config).
__global__ void hist_kernel(const void* __restrict__ ei, int E) {
    int e = blockIdx.x * blockDim.x + threadIdx.x;
    if (e >= E) return;
    int d = g_is64 ? (int)__ldg(&((const long long*)ei)[E + e])
                   : __ldg(&((const int*)ei)[E + e]);
    atomicAdd(&g_deg[d], 1);
}

// scan1: per-block exclusive scan + block totals.
__global__ void __launch_bounds__(SCAN_B)
scan1_kernel(int N) {
    __shared__ int sh[SCAN_B];
    int t = threadIdx.x;
    int i = blockIdx.x * SCAN_B + t;
    int v = (i < N) ? g_deg[i] : 0;
    sh[t] = v;
    __syncthreads();
#pragma unroll
    for (int d = 1; d < SCAN_B; d <<= 1) {
        int u = (t >= d) ? sh[t - d] : 0;
        __syncthreads();
        sh[t] += u;
        __syncthreads();
    }
    if (i < N) g_off[i] = sh[t] - v;
    if (t == SCAN_B - 1) g_bsum[blockIdx.x] = sh[t];
}

// scan23: every block redundantly scans the <=98 block sums in smem, then
// applies its block offset and writes final off/cursor. One launch instead
// of two (kills the 4.8us single-block scan2 latency bubble).
__global__ void __launch_bounds__(256)
scan23_kernel(int N, int E, int NB) {
    __shared__ int sh[128], orig[128];
    int t = threadIdx.x;
    if (t < 128) {
        int v = (t < NB) ? g_bsum[t] : 0;
        sh[t] = v;
        orig[t] = v;
    }
    __syncthreads();
#pragma unroll
    for (int d = 1; d < 128; d <<= 1) {
        int u = (t >= d && t < 128) ? sh[t - d] : 0;
        __syncthreads();
        if (t < 128) sh[t] += u;
        __syncthreads();
    }
    int i = blockIdx.x * blockDim.x + t;
    if (i < N) {
        int b = i >> 10;
        int v = g_off[i] + sh[b] - orig[b];   // exclusive block offset
        g_off[i] = v;
        g_cursor[i] = v;
    }
    if (i == 0) g_off[N] = E;
}

// permute: 1 edge/thread (R11 config).
__global__ void permute_kernel(const void* __restrict__ ei, int E) {
    int e = blockIdx.x * blockDim.x + threadIdx.x;
    if (e >= E) return;
    int s, d;
    if (g_is64) {
        const long long* p = (const long long*)ei;
        s = (int)__ldg(&p[e]);
        d = (int)__ldg(&p[E + e]);
    } else {
        const int* p = (const int*)ei;
        s = __ldg(&p[e]);
        d = __ldg(&p[E + e]);
    }
    int pos = atomicAdd(&g_cursor[d], 1);
    g_srcs[pos] = s;
}

// Warp/node CSR gather; 8-wide load batches (MLP=8); writes h0 as tf32.
__global__ void aggregate_kernel(const float4* __restrict__ x4, int N) {
    int idx = blockIdx.x * blockDim.x + threadIdx.x;
    int node = idx >> 5;
    int lane = idx & 31;
    if (node >= N) return;
    float4 acc = x4[node * 32 + lane];
    const uint2* xh = (const uint2*)g_xh;
    int e = g_off[node], end = g_off[node + 1];
    while (e < end) {
        int cnt = min(32, end - e);
        int myidx = (lane < cnt) ? __ldg(&g_srcs[e + lane]) : 0;
        int j = 0;
        for (; j + 8 <= cnt; j += 8) {
            uint2 p[8];
#pragma unroll
            for (int q = 0; q < 8; q++) {
                int s = __shfl_sync(0xffffffffu, myidx, j + q);
                p[q] = __ldg(&xh[s * 32 + lane]);
            }
#pragma unroll
            for (int q = 0; q < 8; q++) {
                float2 f01 = __half22float2(*(__half2*)&p[q].x);
                float2 f23 = __half22float2(*(__half2*)&p[q].y);
                acc.x += f01.x; acc.y += f01.y;
                acc.z += f23.x; acc.w += f23.y;
            }
        }
        for (; j < cnt; j++) {
            int s = __shfl_sync(0xffffffffu, myidx, j);
            uint2 p = __ldg(&xh[s * 32 + lane]);
            float2 f01 = __half22float2(*(__half2*)&p.x);
            float2 f23 = __half22float2(*(__half2*)&p.y);
            acc.x += f01.x; acc.y += f01.y;
            acc.z += f23.x; acc.w += f23.y;
        }
        e += cnt;
    }
    ((uint4*)g_h0t)[node * 32 + lane] =
        make_uint4(f2tf(acc.x), f2tf(acc.y), f2tf(acc.z), f2tf(acc.w));
}

// ---------------------------------------------------------------------------
// Fused MLP: per 128-row tile: load tf32 h0 -> As -> GEMM1(+b1,relu) -> As
//            -> GEMM2(+b2,relu) -> out + BN stats.
// ---------------------------------------------------------------------------
#define AS_STRIDE 132
#define MLP_SMEM (128 * AS_STRIDE * 4)     // 67584 B

__global__ void __launch_bounds__(512, 2)
mlp_kernel(const float* __restrict__ bias1,
           const float* __restrict__ bias2,
           float* __restrict__ out, int N) {
    extern __shared__ unsigned As[];         // [128][AS_STRIDE]
    const int tid = threadIdx.x;
    const int lane = tid & 31;
    const int wid = tid >> 5;
    const int row0 = blockIdx.x * 128;

    const uint4* H04 = (const uint4*)g_h0t;
#pragma unroll
    for (int i = 0; i < 8; i++) {
        int s = i * 512 + tid;               // 0..4095
        int r = s >> 5, q = s & 31;
        uint4 v = make_uint4(0u, 0u, 0u, 0u);
        int gr = row0 + r;
        if (gr < N) v = H04[gr * 32 + q];
        *(uint4*)&As[r * AS_STRIDE + q * 4] = v;
    }
    __syncthreads();

    const int rg = wid >> 1, cg = wid & 1;
    float d[8][4];
#pragma unroll
    for (int nt = 0; nt < 8; nt++)
#pragma unroll
        for (int r = 0; r < 4; r++) d[nt][r] = 0.f;

    const int rbase = rg * 16 + (lane >> 2);
#pragma unroll
    for (int ksg = 0; ksg < 16; ksg++) {
        int k = ksg * 8 + (lane & 3);
        unsigned a[4];
        a[0] = As[rbase * AS_STRIDE + k];
        a[1] = As[(rbase + 8) * AS_STRIDE + k];
        a[2] = As[rbase * AS_STRIDE + k + 4];
        a[3] = As[(rbase + 8) * AS_STRIDE + k + 4];
#pragma unroll
        for (int nt = 0; nt < 8; nt++) {
            uint2 b = *(const uint2*)&g_w1f[((ksg * 16 + cg * 8 + nt) * 32 + lane) * 2];
            mma_tf32(d[nt], a, b.x, b.y);
        }
    }
    __syncthreads();

    // epilogue 1: bias+relu -> tf32 h1 back into As
#pragma unroll
    for (int nt = 0; nt < 8; nt++) {
        int col = cg * 64 + nt * 8 + 2 * (lane & 3);
        int r0 = rg * 16 + (lane >> 2);
        float b0 = __ldg(&bias1[col]);
        float b1v = __ldg(&bias1[col + 1]);
        float v0 = fmaxf(d[nt][0] + b0, 0.f);
        float v1 = fmaxf(d[nt][1] + b1v, 0.f);
        float v2 = fmaxf(d[nt][2] + b0, 0.f);
        float v3 = fmaxf(d[nt][3] + b1v, 0.f);
        *(uint2*)&As[r0 * AS_STRIDE + col] = make_uint2(f2tf(v0), f2tf(v1));
        *(uint2*)&As[(r0 + 8) * AS_STRIDE + col] = make_uint2(f2tf(v2), f2tf(v3));
#pragma unroll
        for (int r = 0; r < 4; r++) d[nt][r] = 0.f;
    }
    __syncthreads();

    // GEMM2
#pragma unroll
    for (int ksg = 0; ksg < 16; ksg++) {
        int k = ksg * 8 + (lane & 3);
        unsigned a[4];
        a[0] = As[rbase * AS_STRIDE + k];
        a[1] = As[(rbase + 8) * AS_STRIDE + k];
        a[2] = As[rbase * AS_STRIDE + k + 4];
        a[3] = As[(rbase + 8) * AS_STRIDE + k + 4];
#pragma unroll
        for (int nt = 0; nt < 8; nt++) {
            uint2 b = *(const uint2*)&g_w2f[((ksg * 16 + cg * 8 + nt) * 32 + lane) * 2];
            mma_tf32(d[nt], a, b.x, b.y);
        }
    }

    // epilogue 2: bias+relu -> out + BN stats
#pragma unroll
    for (int nt = 0; nt < 8; nt++) {
        int col = cg * 64 + nt * 8 + 2 * (lane & 3);
        int r0 = row0 + rg * 16 + (lane >> 2);
        float b0 = __ldg(&bias2[col]);
        float b1v = __ldg(&bias2[col + 1]);
        float v0 = fmaxf(d[nt][0] + b0, 0.f);
        float v1 = fmaxf(d[nt][1] + b1v, 0.f);
        float v2 = fmaxf(d[nt][2] + b0, 0.f);
        float v3 = fmaxf(d[nt][3] + b1v, 0.f);
        bool ok0 = (r0 < N), ok1 = (r0 + 8 < N);
        if (ok0) *(float2*)&out[r0 * 128 + col] = make_float2(v0, v1);
        if (ok1) *(float2*)&out[(r0 + 8) * 128 + col] = make_float2(v2, v3);
        float s0 = (ok0 ? v0 : 0.f) + (ok1 ? v2 : 0.f);
        float s1 = (ok0 ? v1 : 0.f) + (ok1 ? v3 : 0.f);
        float q0 = (ok0 ? v0 * v0 : 0.f) + (ok1 ? v2 * v2 : 0.f);
        float q1 = (ok0 ? v1 * v1 : 0.f) + (ok1 ? v3 * v3 : 0.f);
#pragma unroll
        for (int m = 16; m >= 4; m >>= 1) {
            s0 += __shfl_xor_sync(0xffffffffu, s0, m);
            s1 += __shfl_xor_sync(0xffffffffu, s1, m);
            q0 += __shfl_xor_sync(0xffffffffu, q0, m);
            q1 += __shfl_xor_sync(0xffffffffu, q1, m);
        }
        if (lane < 4) {
            asm volatile("red.global.add.v2.f32 [%0], {%1, %2};"
                         :: "l"(&g_sum[col]), "f"(s0), "f"(s1) : "memory");
            asm volatile("red.global.add.v2.f32 [%0], {%1, %2};"
                         :: "l"(&g_sq[col]), "f"(q0), "f"(q1) : "memory");
        }
    }
}

// BN apply; per-block recompute of scale/shift from global sums.
__global__ void apply_bn_kernel(float4* __restrict__ out,
                                const float* __restrict__ gamma,
                                const float* __restrict__ beta,
                                float invN, int total4) {
    __shared__ float s_scale[GIN_H], s_shift[GIN_H];
    int t = threadIdx.x;
    if (t < GIN_H) {
        float mean = g_sum[t] * invN;
        float var = fmaf(-mean, mean, g_sq[t] * invN);
        float sc = gamma[t] * rsqrtf(var + 1e-5f);
        s_scale[t] = sc;
        s_shift[t] = fmaf(-mean, sc, beta[t]);
    }
    __syncthreads();
    int idx = blockIdx.x * blockDim.x + t;
    if (idx >= total4) return;
    int c = (idx & 31) * 4;
    float4 v = out[idx];
    v.x = fmaf(v.x, s_scale[c + 0], s_shift[c + 0]);
    v.y = fmaf(v.y, s_scale[c + 1], s_shift[c + 1]);
    v.z = fmaf(v.z, s_scale[c + 2], s_shift[c + 2]);
    v.w = fmaf(v.w, s_scale[c + 3], s_shift[c + 3]);
    out[idx] = v;
}

// ---------------------------------------------------------------------------
// Inputs: x, edge_index, edge_attr, W1, b1, W2, b2, gamma, beta
// ---------------------------------------------------------------------------
extern "C" void kernel_launch(void* const* d_in, const int* in_sizes, int n_in,
                              void* d_out, int out_size) {
    const float* x     = (const float*)d_in[0];
    const void*  ei    = d_in[1];
    const float* W1    = (const float*)d_in[3];
    const float* b1    = (const float*)d_in[4];
    const float* W2    = (const float*)d_in[5];
    const float* b2    = (const float*)d_in[6];
    const float* gamma = (const float*)d_in[7];
    const float* beta  = (const float*)d_in[8];
    float* out = (float*)d_out;

    int N = in_sizes[0] / GIN_H;
    int E = in_sizes[1] / 2;

    cudaFuncSetAttribute(mlp_kernel,
                         cudaFuncAttributeMaxDynamicSharedMemorySize, MLP_SMEM);

    int total4 = N * (GIN_H / 4);
    int eb = (E + 255) / 256;
    int nb = (N + SCAN_B - 1) / SCAN_B;

    prep_kernel<<<(total4 + 255) / 256, 256>>>((const unsigned*)ei,
                                               (const float4*)x, W1, W2, N, total4);
    hist_kernel<<<eb, 256>>>(ei, E);
    scan1_kernel<<<nb, SCAN_B>>>(N);
    scan23_kernel<<<(N + 255) / 256, 256>>>(N, E, nb);
    permute_kernel<<<eb, 256>>>(ei, E);

    long long agg_items = (long long)N * 32;
    aggregate_kernel<<<(int)((agg_items + 255) / 256), 256>>>((const float4*)x, N);

    int tiles = (N + 127) / 128;
    mlp_kernel<<<tiles, 512, MLP_SMEM>>>(b1, b2, out, N);

    apply_bn_kernel<<<(total4 + 255) / 256, 256>>>((float4*)out, gamma, beta,
                                                   1.0f / (float)N, total4);
}

// round 15
// speedup vs baseline: 1.2393x; 1.1880x over previous
#include <cuda_runtime.h>
#include <cuda_fp16.h>

// ---------------------------------------------------------------------------
// GINBlock. R15 (resubmit of R14; container infra failure, 4th occurrence):
// mlp restructure for 4x b-fragment reuse:
//   - 32-row warp tiles (2 a-frags per b-load)
//   - packed uint4 b-frag layout (2 n-tiles per LDG.128)
//   256 threads/CTA, 8 warps, same 128-row tile & smem, 2 CTAs/SM.
// Keep (R13): prep fusion, scan23, 1-edge/thread hist+permute, MLP=8
// aggregate (fp16 gather -> tf32 h0), BN stats via red.v2.
// ---------------------------------------------------------------------------

#define GIN_N_MAX 100000
#define GIN_H 128
#define GIN_E_MAX 3200000
#define SCAN_B 1024
#define SCAN_NB ((GIN_N_MAX + SCAN_B - 1) / SCAN_B)   // 98

__device__ __half   g_xh[GIN_N_MAX * GIN_H];       // fp16 mirror of x
__device__ __align__(16) unsigned g_h0t[GIN_N_MAX * GIN_H];  // h0 in tf32 bits
__device__ int      g_deg[GIN_N_MAX];
__device__ int      g_off[GIN_N_MAX + 1];
__device__ int      g_cursor[GIN_N_MAX];
__device__ int      g_srcs[GIN_E_MAX];
__device__ int      g_bsum[SCAN_NB];
__device__ __align__(16) unsigned g_w1f[16384];    // W1 tf32, packed frag order
__device__ __align__(16) unsigned g_w2f[16384];    // W2 tf32, packed frag order
__device__ __align__(16) float g_sum[GIN_H];
__device__ __align__(16) float g_sq[GIN_H];
__device__ int      g_is64;

__device__ __forceinline__ unsigned f2tf(float f) {
    unsigned r;
    asm("cvt.rna.tf32.f32 %0, %1;" : "=r"(r) : "f"(f));
    return r;
}
__device__ __forceinline__ void mma_tf32(float* d, const unsigned* a, unsigned b0, unsigned b1) {
    asm("mma.sync.aligned.m16n8k8.row.col.f32.tf32.tf32.f32 "
        "{%0,%1,%2,%3}, {%4,%5,%6,%7}, {%8,%9}, {%0,%1,%2,%3};"
        : "+f"(d[0]), "+f"(d[1]), "+f"(d[2]), "+f"(d[3])
        : "r"(a[0]), "r"(a[1]), "r"(a[2]), "r"(a[3]), "r"(b0), "r"(b1));
}

// Packed b-frag slot: sIdx = ((ksg*8 + cg*4 + ntp)*32 + lane), uint4 =
// {b0(ntA), b1(ntA), b0(ntB), b1(ntB)} where ntA=2*ntp, ntB=2*ntp+1.
__device__ __forceinline__ void wfrag_store(unsigned* dst, const float* W, int sIdx) {
    int lane = sIdx & 31;
    int t = sIdx >> 5;
    int ntp = t & 3, cg = (t >> 2) & 1, ksg = t >> 3;
    int k = ksg * 8 + (lane & 3);
    int nA = cg * 64 + (2 * ntp) * 8 + (lane >> 2);
    int nB = nA + 8;
    *(uint4*)&dst[sIdx * 4] = make_uint4(
        f2tf(__ldg(&W[k * 128 + nA])), f2tf(__ldg(&W[(k + 4) * 128 + nA])),
        f2tf(__ldg(&W[k * 128 + nB])), f2tf(__ldg(&W[(k + 4) * 128 + nB])));
}

// ---------------------------------------------------------------------------
// prep: zero deg/sums + int64 sniff + x->fp16 convert + W frag prep, fused.
// ---------------------------------------------------------------------------
__global__ void prep_kernel(const unsigned* __restrict__ ei,
                            const float4* __restrict__ x4,
                            const float* __restrict__ W1,
                            const float* __restrict__ W2,
                            int N, int total4) {
    int idx = blockIdx.x * blockDim.x + threadIdx.x;
    if (idx < N) g_deg[idx] = 0;
    if (idx < GIN_H) { g_sum[idx] = 0.f; g_sq[idx] = 0.f; }
    if (idx == 0) {
        int allz = 1;
#pragma unroll
        for (int i = 0; i < 16; i++) allz &= (ei[2 * i + 1] == 0u);
        g_is64 = allz;
    }
    if (idx < 4096) {   // packed W fragment prep (4096 uint4 slots each)
        wfrag_store(g_w1f, W1, idx);
        wfrag_store(g_w2f, W2, idx);
    }
    if (idx < total4) {  // fp16 mirror
        float4 v = x4[idx];
        __half2 a = __floats2half2_rn(v.x, v.y);
        __half2 b = __floats2half2_rn(v.z, v.w);
        uint2 p;
        p.x = *(unsigned*)&a;
        p.y = *(unsigned*)&b;
        ((uint2*)g_xh)[idx] = p;
    }
}

// hist: 1 edge/thread.
__global__ void hist_kernel(const void* __restrict__ ei, int E) {
    int e = blockIdx.x * blockDim.x + threadIdx.x;
    if (e >= E) return;
    int d = g_is64 ? (int)__ldg(&((const long long*)ei)[E + e])
                   : __ldg(&((const int*)ei)[E + e]);
    atomicAdd(&g_deg[d], 1);
}

// scan1: per-block exclusive scan + block totals.
__global__ void __launch_bounds__(SCAN_B)
scan1_kernel(int N) {
    __shared__ int sh[SCAN_B];
    int t = threadIdx.x;
    int i = blockIdx.x * SCAN_B + t;
    int v = (i < N) ? g_deg[i] : 0;
    sh[t] = v;
    __syncthreads();
#pragma unroll
    for (int d = 1; d < SCAN_B; d <<= 1) {
        int u = (t >= d) ? sh[t - d] : 0;
        __syncthreads();
        sh[t] += u;
        __syncthreads();
    }
    if (i < N) g_off[i] = sh[t] - v;
    if (t == SCAN_B - 1) g_bsum[blockIdx.x] = sh[t];
}

// scan23: every block redundantly scans the <=98 block sums, applies offset.
__global__ void __launch_bounds__(256)
scan23_kernel(int N, int E, int NB) {
    __shared__ int sh[128], orig[128];
    int t = threadIdx.x;
    if (t < 128) {
        int v = (t < NB) ? g_bsum[t] : 0;
        sh[t] = v;
        orig[t] = v;
    }
    __syncthreads();
#pragma unroll
    for (int d = 1; d < 128; d <<= 1) {
        int u = (t >= d && t < 128) ? sh[t - d] : 0;
        __syncthreads();
        if (t < 128) sh[t] += u;
        __syncthreads();
    }
    int i = blockIdx.x * blockDim.x + t;
    if (i < N) {
        int b = i >> 10;
        int v = g_off[i] + sh[b] - orig[b];
        g_off[i] = v;
        g_cursor[i] = v;
    }
    if (i == 0) g_off[N] = E;
}

// permute: 1 edge/thread.
__global__ void permute_kernel(const void* __restrict__ ei, int E) {
    int e = blockIdx.x * blockDim.x + threadIdx.x;
    if (e >= E) return;
    int s, d;
    if (g_is64) {
        const long long* p = (const long long*)ei;
        s = (int)__ldg(&p[e]);
        d = (int)__ldg(&p[E + e]);
    } else {
        const int* p = (const int*)ei;
        s = __ldg(&p[e]);
        d = __ldg(&p[E + e]);
    }
    int pos = atomicAdd(&g_cursor[d], 1);
    g_srcs[pos] = s;
}

// Warp/node CSR gather; 8-wide load batches; writes h0 as tf32.
__global__ void aggregate_kernel(const float4* __restrict__ x4, int N) {
    int idx = blockIdx.x * blockDim.x + threadIdx.x;
    int node = idx >> 5;
    int lane = idx & 31;
    if (node >= N) return;
    float4 acc = x4[node * 32 + lane];
    const uint2* xh = (const uint2*)g_xh;
    int e = g_off[node], end = g_off[node + 1];
    while (e < end) {
        int cnt = min(32, end - e);
        int myidx = (lane < cnt) ? __ldg(&g_srcs[e + lane]) : 0;
        int j = 0;
        for (; j + 8 <= cnt; j += 8) {
            uint2 p[8];
#pragma unroll
            for (int q = 0; q < 8; q++) {
                int s = __shfl_sync(0xffffffffu, myidx, j + q);
                p[q] = __ldg(&xh[s * 32 + lane]);
            }
#pragma unroll
            for (int q = 0; q < 8; q++) {
                float2 f01 = __half22float2(*(__half2*)&p[q].x);
                float2 f23 = __half22float2(*(__half2*)&p[q].y);
                acc.x += f01.x; acc.y += f01.y;
                acc.z += f23.x; acc.w += f23.y;
            }
        }
        for (; j < cnt; j++) {
            int s = __shfl_sync(0xffffffffu, myidx, j);
            uint2 p = __ldg(&xh[s * 32 + lane]);
            float2 f01 = __half22float2(*(__half2*)&p.x);
            float2 f23 = __half22float2(*(__half2*)&p.y);
            acc.x += f01.x; acc.y += f01.y;
            acc.z += f23.x; acc.w += f23.y;
        }
        e += cnt;
    }
    ((uint4*)g_h0t)[node * 32 + lane] =
        make_uint4(f2tf(acc.x), f2tf(acc.y), f2tf(acc.z), f2tf(acc.w));
}

// ---------------------------------------------------------------------------
// Fused MLP: 256 threads = 8 warps; rg=wid>>1 (32-row group), cg=wid&1.
// Warp tile 32 rows x 64 cols: f=2 a-frags, packed uint4 b-frags (2 n-tiles).
// ---------------------------------------------------------------------------
#define AS_STRIDE 132
#define MLP_SMEM (128 * AS_STRIDE * 4)     // 67584 B

__global__ void __launch_bounds__(256, 2)
mlp_kernel(const float* __restrict__ bias1,
           const float* __restrict__ bias2,
           float* __restrict__ out, int N) {
    extern __shared__ unsigned As[];         // [128][AS_STRIDE]
    const int tid = threadIdx.x;
    const int lane = tid & 31;
    const int wid = tid >> 5;
    const int row0 = blockIdx.x * 128;

    // stage tf32 h0 tile (coalesced uint4); 4096 slots / 256 threads = 16 it
    const uint4* H04 = (const uint4*)g_h0t;
#pragma unroll
    for (int i = 0; i < 16; i++) {
        int s = i * 256 + tid;               // 0..4095
        int r = s >> 5, q = s & 31;
        uint4 v = make_uint4(0u, 0u, 0u, 0u);
        int gr = row0 + r;
        if (gr < N) v = H04[gr * 32 + q];
        *(uint4*)&As[r * AS_STRIDE + q * 4] = v;
    }
    __syncthreads();

    const int rg = wid >> 1, cg = wid & 1;   // rg 0..3 (32 rows), cg 0..1
    float d[2][8][4];
#pragma unroll
    for (int f = 0; f < 2; f++)
#pragma unroll
        for (int nt = 0; nt < 8; nt++)
#pragma unroll
            for (int r = 0; r < 4; r++) d[f][nt][r] = 0.f;

    // ---- GEMM1 ----
#pragma unroll
    for (int ksg = 0; ksg < 16; ksg++) {
        int k = ksg * 8 + (lane & 3);
        unsigned a[2][4];
#pragma unroll
        for (int f = 0; f < 2; f++) {
            int rb = rg * 32 + f * 16 + (lane >> 2);
            a[f][0] = As[rb * AS_STRIDE + k];
            a[f][1] = As[(rb + 8) * AS_STRIDE + k];
            a[f][2] = As[rb * AS_STRIDE + k + 4];
            a[f][3] = As[(rb + 8) * AS_STRIDE + k + 4];
        }
#pragma unroll
        for (int ntp = 0; ntp < 4; ntp++) {
            uint4 b = *(const uint4*)&g_w1f[(((ksg * 8 + cg * 4 + ntp) * 32 + lane)) * 4];
            mma_tf32(d[0][2 * ntp], a[0], b.x, b.y);
            mma_tf32(d[1][2 * ntp], a[1], b.x, b.y);
            mma_tf32(d[0][2 * ntp + 1], a[0], b.z, b.w);
            mma_tf32(d[1][2 * ntp + 1], a[1], b.z, b.w);
        }
    }
    __syncthreads();

    // epilogue 1: bias+relu -> tf32 h1 back into As
#pragma unroll
    for (int f = 0; f < 2; f++)
#pragma unroll
        for (int nt = 0; nt < 8; nt++) {
            int col = cg * 64 + nt * 8 + 2 * (lane & 3);
            int r0 = rg * 32 + f * 16 + (lane >> 2);
            float b0 = __ldg(&bias1[col]);
            float b1v = __ldg(&bias1[col + 1]);
            float v0 = fmaxf(d[f][nt][0] + b0, 0.f);
            float v1 = fmaxf(d[f][nt][1] + b1v, 0.f);
            float v2 = fmaxf(d[f][nt][2] + b0, 0.f);
            float v3 = fmaxf(d[f][nt][3] + b1v, 0.f);
            *(uint2*)&As[r0 * AS_STRIDE + col] = make_uint2(f2tf(v0), f2tf(v1));
            *(uint2*)&As[(r0 + 8) * AS_STRIDE + col] = make_uint2(f2tf(v2), f2tf(v3));
#pragma unroll
            for (int r = 0; r < 4; r++) d[f][nt][r] = 0.f;
        }
    __syncthreads();

    // ---- GEMM2 ----
#pragma unroll
    for (int ksg = 0; ksg < 16; ksg++) {
        int k = ksg * 8 + (lane & 3);
        unsigned a[2][4];
#pragma unroll
        for (int f = 0; f < 2; f++) {
            int rb = rg * 32 + f * 16 + (lane >> 2);
            a[f][0] = As[rb * AS_STRIDE + k];
            a[f][1] = As[(rb + 8) * AS_STRIDE + k];
            a[f][2] = As[rb * AS_STRIDE + k + 4];
            a[f][3] = As[(rb + 8) * AS_STRIDE + k + 4];
        }
#pragma unroll
        for (int ntp = 0; ntp < 4; ntp++) {
            uint4 b = *(const uint4*)&g_w2f[(((ksg * 8 + cg * 4 + ntp) * 32 + lane)) * 4];
            mma_tf32(d[0][2 * ntp], a[0], b.x, b.y);
            mma_tf32(d[1][2 * ntp], a[1], b.x, b.y);
            mma_tf32(d[0][2 * ntp + 1], a[0], b.z, b.w);
            mma_tf32(d[1][2 * ntp + 1], a[1], b.z, b.w);
        }
    }

    // epilogue 2: bias+relu -> out + BN stats (reduced across both f)
#pragma unroll
    for (int nt = 0; nt < 8; nt++) {
        int col = cg * 64 + nt * 8 + 2 * (lane & 3);
        float b0 = __ldg(&bias2[col]);
        float b1v = __ldg(&bias2[col + 1]);
        float s0 = 0.f, s1 = 0.f, q0 = 0.f, q1 = 0.f;
#pragma unroll
        for (int f = 0; f < 2; f++) {
            int r0 = row0 + rg * 32 + f * 16 + (lane >> 2);
            float v0 = fmaxf(d[f][nt][0] + b0, 0.f);
            float v1 = fmaxf(d[f][nt][1] + b1v, 0.f);
            float v2 = fmaxf(d[f][nt][2] + b0, 0.f);
            float v3 = fmaxf(d[f][nt][3] + b1v, 0.f);
            bool ok0 = (r0 < N), ok1 = (r0 + 8 < N);
            if (ok0) *(float2*)&out[r0 * 128 + col] = make_float2(v0, v1);
            if (ok1) *(float2*)&out[(r0 + 8) * 128 + col] = make_float2(v2, v3);
            s0 += (ok0 ? v0 : 0.f) + (ok1 ? v2 : 0.f);
            s1 += (ok0 ? v1 : 0.f) + (ok1 ? v3 : 0.f);
            q0 += (ok0 ? v0 * v0 : 0.f) + (ok1 ? v2 * v2 : 0.f);
            q1 += (ok0 ? v1 * v1 : 0.f) + (ok1 ? v3 * v3 : 0.f);
        }
#pragma unroll
        for (int m = 16; m >= 4; m >>= 1) {
            s0 += __shfl_xor_sync(0xffffffffu, s0, m);
            s1 += __shfl_xor_sync(0xffffffffu, s1, m);
            q0 += __shfl_xor_sync(0xffffffffu, q0, m);
            q1 += __shfl_xor_sync(0xffffffffu, q1, m);
        }
        if (lane < 4) {
            asm volatile("red.global.add.v2.f32 [%0], {%1, %2};"
                         :: "l"(&g_sum[col]), "f"(s0), "f"(s1) : "memory");
            asm volatile("red.global.add.v2.f32 [%0], {%1, %2};"
                         :: "l"(&g_sq[col]), "f"(q0), "f"(q1) : "memory");
        }
    }
}

// BN apply; per-block recompute of scale/shift from global sums.
__global__ void apply_bn_kernel(float4* __restrict__ out,
                                const float* __restrict__ gamma,
                                const float* __restrict__ beta,
                                float invN, int total4) {
    __shared__ float s_scale[GIN_H], s_shift[GIN_H];
    int t = threadIdx.x;
    if (t < GIN_H) {
        float mean = g_sum[t] * invN;
        float var = fmaf(-mean, mean, g_sq[t] * invN);
        float sc = gamma[t] * rsqrtf(var + 1e-5f);
        s_scale[t] = sc;
        s_shift[t] = fmaf(-mean, sc, beta[t]);
    }
    __syncthreads();
    int idx = blockIdx.x * blockDim.x + t;
    if (idx >= total4) return;
    int c = (idx & 31) * 4;
    float4 v = out[idx];
    v.x = fmaf(v.x, s_scale[c + 0], s_shift[c + 0]);
    v.y = fmaf(v.y, s_scale[c + 1], s_shift[c + 1]);
    v.z = fmaf(v.z, s_scale[c + 2], s_shift[c + 2]);
    v.w = fmaf(v.w, s_scale[c + 3], s_shift[c + 3]);
    out[idx] = v;
}

// ---------------------------------------------------------------------------
// Inputs: x, edge_index, edge_attr, W1, b1, W2, b2, gamma, beta
// ---------------------------------------------------------------------------
extern "C" void kernel_launch(void* const* d_in, const int* in_sizes, int n_in,
                              void* d_out, int out_size) {
    const float* x     = (const float*)d_in[0];
    const void*  ei    = d_in[1];
    const float* W1    = (const float*)d_in[3];
    const float* b1    = (const float*)d_in[4];
    const float* W2    = (const float*)d_in[5];
    const float* b2    = (const float*)d_in[6];
    const float* gamma = (const float*)d_in[7];
    const float* beta  = (const float*)d_in[8];
    float* out = (float*)d_out;

    int N = in_sizes[0] / GIN_H;
    int E = in_sizes[1] / 2;

    cudaFuncSetAttribute(mlp_kernel,
                         cudaFuncAttributeMaxDynamicSharedMemorySize, MLP_SMEM);

    int total4 = N * (GIN_H / 4);
    int eb = (E + 255) / 256;
    int nb = (N + SCAN_B - 1) / SCAN_B;

    prep_kernel<<<(total4 + 255) / 256, 256>>>((const unsigned*)ei,
                                               (const float4*)x, W1, W2, N, total4);
    hist_kernel<<<eb, 256>>>(ei, E);
    scan1_kernel<<<nb, SCAN_B>>>(N);
    scan23_kernel<<<(N + 255) / 256, 256>>>(N, E, nb);
    permute_kernel<<<eb, 256>>>(ei, E);

    long long agg_items = (long long)N * 32;
    aggregate_kernel<<<(int)((agg_items + 255) / 256), 256>>>((const float4*)x, N);

    int tiles = (N + 127) / 128;
    mlp_kernel<<<tiles, 256, MLP_SMEM>>>(b1, b2, out, N);

    apply_bn_kernel<<<(total4 + 255) / 256, 256>>>((float4*)out, gamma, beta,
                                                   1.0f / (float)N, total4);
}